// round 2
// baseline (speedup 1.0000x reference)
#include <cuda_runtime.h>

#define N_NODES 50000
#define E_EDGES 1600000
#define M_TOTAL (E_EDGES + N_NODES)

// Scratch: per-node max-aggregated features [N, 64]. Device global => no allocation.
__device__ float g_agg[N_NODES * 64];
// Edge-index dtype flag: 1 if buffer is int64, 0 if int32. Set by k_detect each run.
__device__ int g_ei_is64;

// ---------------------------------------------------------------------------
// Kernel D: detect edge_index dtype. If int64 (little-endian, values<50000),
// all odd 32-bit words are 0. If int32 edge list, odd words are dst indices
// (prob. all-zero over 2048 samples ~ 0).
// ---------------------------------------------------------------------------
__global__ void k_detect(const int* __restrict__ ei_raw) {
    __shared__ int any_nonzero;
    if (threadIdx.x == 0) any_nonzero = 0;
    __syncthreads();
    int w = ei_raw[2 * threadIdx.x + 1 + 2048 * blockIdx.x * 0];
    if (w != 0) atomicOr(&any_nonzero, 1);
    __syncthreads();
    if (threadIdx.x == 0) g_ei_is64 = any_nonzero ? 0 : 1;
}

// ---------------------------------------------------------------------------
// Kernel 0: zero the aggregation buffer (3.2M floats = 800K float4)
// ---------------------------------------------------------------------------
__global__ void k_zero() {
    int i = blockIdx.x * blockDim.x + threadIdx.x;
    if (i < N_NODES * 64 / 4)
        ((float4*)g_agg)[i] = make_float4(0.f, 0.f, 0.f, 0.f);
}

// ---------------------------------------------------------------------------
// Kernel 1: fused message MLP + max scatter.
// Tile: 128 messages per block, 128 threads, each thread computes an
// 8-messages x 8-features register tile.
// Messages m < E are edges; m in [E, E+N) are self-loops (pos diff = 0).
// ---------------------------------------------------------------------------
#define TILE_E 128

// dynamic smem layout (in floats)
#define SM_W1   0                       // 35*64 = 2240
#define SM_W2   (SM_W1 + 35 * 64)       // 64*64 = 4096
#define SM_MSG  (SM_W2 + 64 * 64)       // 128*36 = 4608  (stride 36)
#define SM_H1   (SM_MSG + 128 * 36)     // 128*68 = 8704  (stride 68)
#define SM_DST  (SM_H1 + 128 * 68)      // 128 ints
#define SMEM_MSG_BYTES ((SM_DST + 128) * 4)   // 79104 bytes

__device__ __forceinline__ int clampN(int v) {
    // clamp to [0, N_NODES-1] via unsigned trick + min
    unsigned u = (unsigned)v;
    return (u < N_NODES) ? v : (v < 0 ? 0 : N_NODES - 1);
}

__global__ __launch_bounds__(128) void k_msg(
    const float* __restrict__ x,        // [N, 32]
    const float* __restrict__ pos,      // [N, 3]
    const void* __restrict__ ei_raw,    // [2, E] int32 or int64
    const float* __restrict__ W1,       // [35, 64]
    const float* __restrict__ b1,       // [64]
    const float* __restrict__ W2,       // [64, 64]
    const float* __restrict__ b2)       // [64]
{
    extern __shared__ float sm[];
    float* sW1  = sm + SM_W1;
    float* sW2  = sm + SM_W2;
    float* sMsg = sm + SM_MSG;
    float* sH1  = sm + SM_H1;
    int*   sDst = (int*)(sm + SM_DST);

    const int tid = threadIdx.x;

    // Stage weights into smem
    for (int i = tid; i < 35 * 64; i += 128) sW1[i] = W1[i];
    for (int i = tid; i < 64 * 64; i += 128) sW2[i] = W2[i];

    // Gather: one message per thread
    {
        int m = blockIdx.x * TILE_E + tid;
        int src = 0, dst = -1;
        if (m < E_EDGES) {
            if (g_ei_is64) {
                const long long* e64 = (const long long*)ei_raw;
                src = (int)e64[m];
                dst = (int)e64[E_EDGES + m];
            } else {
                const int* e32 = (const int*)ei_raw;
                src = e32[m];
                dst = e32[E_EDGES + m];
            }
            src = clampN(src);
            dst = clampN(dst);
        } else if (m < M_TOTAL) {
            src = m - E_EDGES; dst = src;
        }
        sDst[tid] = dst;
        int s = (dst >= 0) ? src : 0;
        int d = (dst >= 0) ? dst : 0;

        const float4* xr = (const float4*)(x + (size_t)s * 32);
        float4* mrow = (float4*)(sMsg + tid * 36);
        #pragma unroll
        for (int q = 0; q < 8; q++) mrow[q] = __ldg(xr + q);
        sMsg[tid * 36 + 32] = pos[s * 3 + 0] - pos[d * 3 + 0];
        sMsg[tid * 36 + 33] = pos[s * 3 + 1] - pos[d * 3 + 1];
        sMsg[tid * 36 + 34] = pos[s * 3 + 2] - pos[d * 3 + 2];
    }
    __syncthreads();

    const int tx = tid & 7;     // 8 feature groups of 8
    const int ty = tid >> 3;    // 16 message groups; msg index = ty + 16*i
    const int fbase = tx * 8;

    float acc[8][8];
    float bj[8];

    // ---- GEMM1: H1 = relu(msg @ W1 + b1), K = 35 ----
    #pragma unroll
    for (int j = 0; j < 8; j++) bj[j] = __ldg(&b1[fbase + j]);
    #pragma unroll
    for (int i = 0; i < 8; i++)
        #pragma unroll
        for (int j = 0; j < 8; j++) acc[i][j] = bj[j];

    for (int k = 0; k < 35; k++) {
        float4 w0 = *(const float4*)(sW1 + k * 64 + fbase);
        float4 w1 = *(const float4*)(sW1 + k * 64 + fbase + 4);
        float wv[8] = {w0.x, w0.y, w0.z, w0.w, w1.x, w1.y, w1.z, w1.w};
        #pragma unroll
        for (int i = 0; i < 8; i++) {
            float mv = sMsg[(ty + 16 * i) * 36 + k];
            #pragma unroll
            for (int j = 0; j < 8; j++) acc[i][j] = fmaf(mv, wv[j], acc[i][j]);
        }
    }

    // relu -> sH1 (stride 68 to dodge bank conflicts on the k-reads)
    #pragma unroll
    for (int i = 0; i < 8; i++) {
        float4 v0, v1;
        v0.x = fmaxf(acc[i][0], 0.f); v0.y = fmaxf(acc[i][1], 0.f);
        v0.z = fmaxf(acc[i][2], 0.f); v0.w = fmaxf(acc[i][3], 0.f);
        v1.x = fmaxf(acc[i][4], 0.f); v1.y = fmaxf(acc[i][5], 0.f);
        v1.z = fmaxf(acc[i][6], 0.f); v1.w = fmaxf(acc[i][7], 0.f);
        *(float4*)(sH1 + (ty + 16 * i) * 68 + fbase)     = v0;
        *(float4*)(sH1 + (ty + 16 * i) * 68 + fbase + 4) = v1;
    }
    __syncthreads();

    // ---- GEMM2: H2 = relu(H1 @ W2 + b2), K = 64 ----
    #pragma unroll
    for (int j = 0; j < 8; j++) bj[j] = __ldg(&b2[fbase + j]);
    #pragma unroll
    for (int i = 0; i < 8; i++)
        #pragma unroll
        for (int j = 0; j < 8; j++) acc[i][j] = bj[j];

    for (int k = 0; k < 64; k++) {
        float4 w0 = *(const float4*)(sW2 + k * 64 + fbase);
        float4 w1 = *(const float4*)(sW2 + k * 64 + fbase + 4);
        float wv[8] = {w0.x, w0.y, w0.z, w0.w, w1.x, w1.y, w1.z, w1.w};
        #pragma unroll
        for (int i = 0; i < 8; i++) {
            float hv = sH1[(ty + 16 * i) * 68 + k];
            #pragma unroll
            for (int j = 0; j < 8; j++) acc[i][j] = fmaf(hv, wv[j], acc[i][j]);
        }
    }

    // ---- relu + max scatter. Values >= 0 so signed-int atomicMax on the
    // float bit pattern is order-preserving (accumulator zero-initialized). ----
    #pragma unroll
    for (int i = 0; i < 8; i++) {
        int dst = sDst[ty + 16 * i];
        if (dst >= 0) {
            int* ap = (int*)(g_agg + (size_t)dst * 64 + fbase);
            #pragma unroll
            for (int j = 0; j < 8; j++)
                atomicMax(ap + j, __float_as_int(fmaxf(acc[i][j], 0.f)));
        }
    }
}

// ---------------------------------------------------------------------------
// Kernel 2: out = agg @ Wg + bg    [50000,64] x [64,128]
// Tile: 64 nodes x 128 feats, 128 threads, 8x8 per-thread tile.
// ---------------------------------------------------------------------------
#define SMO_A 0                       // 64*68 (stride 68)
#define SMO_W (64 * 68)               // 64*128
#define SMEM_OUT_BYTES ((64 * 68 + 64 * 128) * 4)   // 50176 bytes

__global__ __launch_bounds__(128) void k_out(
    const float* __restrict__ Wg,     // [64, 128]
    const float* __restrict__ bg,     // [128]
    float* __restrict__ out)          // [N, 128]
{
    extern __shared__ float sm[];
    float* sA = sm + SMO_A;
    float* sW = sm + SMO_W;
    const int tid = threadIdx.x;
    const int nbase = blockIdx.x * 64;

    // Stage full Wg (8192 floats)
    {
        float4* dst4 = (float4*)sW;
        const float4* src4 = (const float4*)Wg;
        for (int i = tid; i < 64 * 32; i += 128) dst4[i] = __ldg(src4 + i);
    }
    // Stage agg tile [64, 64] -> stride 68
    for (int idx = tid; idx < 64 * 16; idx += 128) {
        int r = idx >> 4, c4 = idx & 15;
        float4 v = make_float4(0.f, 0.f, 0.f, 0.f);
        if (nbase + r < N_NODES)
            v = *(const float4*)(g_agg + (size_t)(nbase + r) * 64 + c4 * 4);
        *(float4*)(sA + r * 68 + c4 * 4) = v;
    }
    __syncthreads();

    const int tx = tid & 15;    // 16 feature groups of 8 (=128)
    const int ty = tid >> 4;    // 8 node groups; node = ty + 8*i
    const int fbase = tx * 8;

    float acc[8][8];
    float bj[8];
    #pragma unroll
    for (int j = 0; j < 8; j++) bj[j] = __ldg(&bg[fbase + j]);
    #pragma unroll
    for (int i = 0; i < 8; i++)
        #pragma unroll
        for (int j = 0; j < 8; j++) acc[i][j] = bj[j];

    for (int k = 0; k < 64; k++) {
        float4 w0 = *(const float4*)(sW + k * 128 + fbase);
        float4 w1 = *(const float4*)(sW + k * 128 + fbase + 4);
        float wv[8] = {w0.x, w0.y, w0.z, w0.w, w1.x, w1.y, w1.z, w1.w};
        #pragma unroll
        for (int i = 0; i < 8; i++) {
            float av = sA[(ty + 8 * i) * 68 + k];
            #pragma unroll
            for (int j = 0; j < 8; j++) acc[i][j] = fmaf(av, wv[j], acc[i][j]);
        }
    }

    #pragma unroll
    for (int i = 0; i < 8; i++) {
        int n = nbase + ty + 8 * i;
        if (n < N_NODES) {
            float4 v0, v1;
            v0.x = acc[i][0]; v0.y = acc[i][1]; v0.z = acc[i][2]; v0.w = acc[i][3];
            v1.x = acc[i][4]; v1.y = acc[i][5]; v1.z = acc[i][6]; v1.w = acc[i][7];
            *(float4*)(out + (size_t)n * 128 + fbase)     = v0;
            *(float4*)(out + (size_t)n * 128 + fbase + 4) = v1;
        }
    }
}

// ---------------------------------------------------------------------------
extern "C" void kernel_launch(void* const* d_in, const int* in_sizes, int n_in,
                              void* d_out, int out_size) {
    const float* x   = (const float*)d_in[0];
    const float* pos = (const float*)d_in[1];
    const void*  ei  = d_in[2];
    const float* W1  = (const float*)d_in[3];
    const float* b1  = (const float*)d_in[4];
    const float* W2  = (const float*)d_in[5];
    const float* b2  = (const float*)d_in[6];
    const float* Wg  = (const float*)d_in[7];
    const float* bg  = (const float*)d_in[8];
    float* out = (float*)d_out;

    // > 48KB dynamic smem opt-in (idempotent, no allocation)
    cudaFuncSetAttribute(k_msg, cudaFuncAttributeMaxDynamicSharedMemorySize, SMEM_MSG_BYTES);
    cudaFuncSetAttribute(k_out, cudaFuncAttributeMaxDynamicSharedMemorySize, SMEM_OUT_BYTES);

    k_detect<<<1, 1024>>>((const int*)ei);
    k_zero<<<(N_NODES * 64 / 4 + 255) / 256, 256>>>();
    k_msg<<<(M_TOTAL + TILE_E - 1) / TILE_E, 128, SMEM_MSG_BYTES>>>(x, pos, ei, W1, b1, W2, b2);
    k_out<<<(N_NODES + 63) / 64, 128, SMEM_OUT_BYTES>>>(Wg, bg, out);
}

// round 4
// speedup vs baseline: 1.2471x; 1.2471x over previous
#include <cuda_runtime.h>
#include <cstdint>

#define N_NODES 50000
#define E_EDGES 1600000
#define M_TOTAL (E_EDGES + N_NODES)

__device__ float g_agg[N_NODES * 64];
__device__ int g_ei_is64;

// ---------------------------------------------------------------------------
__global__ void k_detect(const int* __restrict__ ei_raw) {
    __shared__ int any_nonzero;
    if (threadIdx.x == 0) any_nonzero = 0;
    __syncthreads();
    int w = ei_raw[2 * threadIdx.x + 1];
    if (w != 0) atomicOr(&any_nonzero, 1);
    __syncthreads();
    if (threadIdx.x == 0) g_ei_is64 = any_nonzero ? 0 : 1;
}

__global__ void k_zero() {
    int i = blockIdx.x * blockDim.x + threadIdx.x;
    if (i < N_NODES * 64 / 4)
        ((float4*)g_agg)[i] = make_float4(0.f, 0.f, 0.f, 0.f);
}

// ---------------------------------------------------------------------------
// Kernel 1: fused message MLP + max scatter. 128 msgs/block, 128 threads,
// 8x8 per-thread register tile, k-unrolled x4 with vectorized smem loads.
// ---------------------------------------------------------------------------
#define TILE_E 128

// smem layout (floats)
#define SM_W1   0                       // 36*64 = 2304 (row 35 zeroed)
#define SM_W2   (SM_W1 + 36 * 64)       // 64*64 = 4096
#define SM_MSG  (SM_W2 + 64 * 64)       // 128*36 (stride 36, [35]=0)
#define SM_H1   (SM_MSG + 128 * 36)     // 128*68 (stride 68) - reused as sOut
#define SM_DST  (SM_H1 + 128 * 68)      // 128 ints
#define SMEM_MSG_BYTES ((SM_DST + 128) * 4)   // 79,424 bytes

__global__ __launch_bounds__(128, 2) void k_msg(
    const float* __restrict__ x,        // [N, 32]
    const float* __restrict__ pos,      // [N, 3]
    const void* __restrict__ ei_raw,    // [2, E] int32 or int64
    const float* __restrict__ W1,       // [35, 64]
    const float* __restrict__ b1,       // [64]
    const float* __restrict__ W2,       // [64, 64]
    const float* __restrict__ b2)       // [64]
{
    extern __shared__ float sm[];
    float* sW1  = sm + SM_W1;
    float* sW2  = sm + SM_W2;
    float* sMsg = sm + SM_MSG;
    float* sH1  = sm + SM_H1;
    int*   sDst = (int*)(sm + SM_DST);

    const int tid = threadIdx.x;
    const int wid = tid >> 5;
    const int lid = tid & 31;

    // Stage weights (W1 padded to 36 rows, row 35 = 0)
    for (int i = tid; i < 36 * 64; i += 128) {
        int k = i >> 6;
        sW1[i] = (k < 35) ? W1[i] : 0.f;
    }
    for (int i = tid; i < 64 * 64; i += 128) sW2[i] = W2[i];

    // Gather: one message per thread
    {
        int m = blockIdx.x * TILE_E + tid;
        int src = 0, dst = -1;
        if (m < E_EDGES) {
            if (g_ei_is64) {
                const long long* e = (const long long*)ei_raw;
                src = (int)e[m]; dst = (int)e[E_EDGES + m];
            } else {
                const int* e = (const int*)ei_raw;
                src = e[m]; dst = e[E_EDGES + m];
            }
            if ((unsigned)src >= N_NODES) src = 0;
            if ((unsigned)dst >= N_NODES) dst = 0;
        } else if (m < M_TOTAL) {
            src = m - E_EDGES; dst = src;
        }
        sDst[tid] = dst;
        int s = (dst >= 0) ? src : 0;
        int d = (dst >= 0) ? dst : 0;

        const float4* xr = (const float4*)(x + (size_t)s * 32);
        float4* mrow = (float4*)(sMsg + tid * 36);
        #pragma unroll
        for (int q = 0; q < 8; q++) mrow[q] = __ldg(xr + q);
        sMsg[tid * 36 + 32] = pos[s * 3 + 0] - pos[d * 3 + 0];
        sMsg[tid * 36 + 33] = pos[s * 3 + 1] - pos[d * 3 + 1];
        sMsg[tid * 36 + 34] = pos[s * 3 + 2] - pos[d * 3 + 2];
        sMsg[tid * 36 + 35] = 0.f;
    }
    __syncthreads();

    const int tx = tid & 7;     // 8 feature groups of 8
    const int ty = tid >> 3;    // 16 message groups; msg row = ty + 16*i
    const int fbase = tx * 8;

    float acc[8][8];

    // ---- GEMM1: H1 = relu(msg @ W1 + b1), K = 36 (padded), unroll 4 ----
    {
        float bj[8];
        #pragma unroll
        for (int j = 0; j < 8; j++) bj[j] = __ldg(&b1[fbase + j]);
        #pragma unroll
        for (int i = 0; i < 8; i++)
            #pragma unroll
            for (int j = 0; j < 8; j++) acc[i][j] = bj[j];

        for (int k4 = 0; k4 < 9; k4++) {
            const int k0 = k4 * 4;
            float4 wv[4][2];
            #pragma unroll
            for (int kk = 0; kk < 4; kk++) {
                wv[kk][0] = *(const float4*)(sW1 + (k0 + kk) * 64 + fbase);
                wv[kk][1] = *(const float4*)(sW1 + (k0 + kk) * 64 + fbase + 4);
            }
            #pragma unroll
            for (int i = 0; i < 8; i++) {
                float4 mv = *(const float4*)(sMsg + (ty + 16 * i) * 36 + k0);
                float m4[4] = {mv.x, mv.y, mv.z, mv.w};
                #pragma unroll
                for (int kk = 0; kk < 4; kk++) {
                    const float* w = &wv[kk][0].x;
                    #pragma unroll
                    for (int j = 0; j < 8; j++)
                        acc[i][j] = fmaf(m4[kk], w[j], acc[i][j]);
                }
            }
        }
    }

    // relu -> sH1 (stride 68)
    #pragma unroll
    for (int i = 0; i < 8; i++) {
        float4 v0, v1;
        v0.x = fmaxf(acc[i][0], 0.f); v0.y = fmaxf(acc[i][1], 0.f);
        v0.z = fmaxf(acc[i][2], 0.f); v0.w = fmaxf(acc[i][3], 0.f);
        v1.x = fmaxf(acc[i][4], 0.f); v1.y = fmaxf(acc[i][5], 0.f);
        v1.z = fmaxf(acc[i][6], 0.f); v1.w = fmaxf(acc[i][7], 0.f);
        *(float4*)(sH1 + (ty + 16 * i) * 68 + fbase)     = v0;
        *(float4*)(sH1 + (ty + 16 * i) * 68 + fbase + 4) = v1;
    }
    __syncthreads();

    // ---- GEMM2: H2 = relu(H1 @ W2 + b2), K = 64, unroll 4 ----
    {
        float bj[8];
        #pragma unroll
        for (int j = 0; j < 8; j++) bj[j] = __ldg(&b2[fbase + j]);
        #pragma unroll
        for (int i = 0; i < 8; i++)
            #pragma unroll
            for (int j = 0; j < 8; j++) acc[i][j] = bj[j];

        for (int k4 = 0; k4 < 16; k4++) {
            const int k0 = k4 * 4;
            float4 wv[4][2];
            #pragma unroll
            for (int kk = 0; kk < 4; kk++) {
                wv[kk][0] = *(const float4*)(sW2 + (k0 + kk) * 64 + fbase);
                wv[kk][1] = *(const float4*)(sW2 + (k0 + kk) * 64 + fbase + 4);
            }
            #pragma unroll
            for (int i = 0; i < 8; i++) {
                float4 hv = *(const float4*)(sH1 + (ty + 16 * i) * 68 + k0);
                float h4[4] = {hv.x, hv.y, hv.z, hv.w};
                #pragma unroll
                for (int kk = 0; kk < 4; kk++) {
                    const float* w = &wv[kk][0].x;
                    #pragma unroll
                    for (int j = 0; j < 8; j++)
                        acc[i][j] = fmaf(h4[kk], w[j], acc[i][j]);
                }
            }
        }
    }
    __syncthreads();   // all GEMM2 reads of sH1 done before we overwrite it

    // stage relu(H2) -> sH1 reused as sOut (stride 68)
    #pragma unroll
    for (int i = 0; i < 8; i++) {
        float4 v0, v1;
        v0.x = fmaxf(acc[i][0], 0.f); v0.y = fmaxf(acc[i][1], 0.f);
        v0.z = fmaxf(acc[i][2], 0.f); v0.w = fmaxf(acc[i][3], 0.f);
        v1.x = fmaxf(acc[i][4], 0.f); v1.y = fmaxf(acc[i][5], 0.f);
        v1.z = fmaxf(acc[i][6], 0.f); v1.w = fmaxf(acc[i][7], 0.f);
        *(float4*)(sH1 + (ty + 16 * i) * 68 + fbase)     = v0;
        *(float4*)(sH1 + (ty + 16 * i) * 68 + fbase + 4) = v1;
    }
    __syncthreads();

    // ---- coalesced max scatter: warp per message, lanes = consecutive feats.
    // One 128B line per REDG; predicated on v>0 (agg zero-initialized; values
    // are ReLU outputs >= 0 so signed-int max on bits is order-preserving). ----
    for (int m = wid; m < TILE_E; m += 4) {
        int dst = sDst[m];
        if (dst < 0) continue;
        float v0 = sH1[m * 68 + lid];
        float v1 = sH1[m * 68 + 32 + lid];
        int* ap = (int*)g_agg + (size_t)dst * 64;
        if (v0 > 0.f) atomicMax(ap + lid,      __float_as_int(v0));
        if (v1 > 0.f) atomicMax(ap + 32 + lid, __float_as_int(v1));
    }
}

// ---------------------------------------------------------------------------
// Kernel 2: out = agg @ Wg + bg    [50000,64] x [64,128]
// ---------------------------------------------------------------------------
#define SMO_A 0
#define SMO_W (64 * 68)
#define SMEM_OUT_BYTES ((64 * 68 + 64 * 128) * 4)

__global__ __launch_bounds__(128) void k_out(
    const float* __restrict__ Wg, const float* __restrict__ bg,
    float* __restrict__ out)
{
    extern __shared__ float sm[];
    float* sA = sm + SMO_A;
    float* sW = sm + SMO_W;
    const int tid = threadIdx.x;
    const int nbase = blockIdx.x * 64;

    {
        float4* dst4 = (float4*)sW;
        const float4* src4 = (const float4*)Wg;
        for (int i = tid; i < 64 * 32; i += 128) dst4[i] = __ldg(src4 + i);
    }
    for (int idx = tid; idx < 64 * 16; idx += 128) {
        int rr = idx >> 4, c4 = idx & 15;
        float4 v = make_float4(0.f, 0.f, 0.f, 0.f);
        if (nbase + rr < N_NODES)
            v = *(const float4*)(g_agg + (size_t)(nbase + rr) * 64 + c4 * 4);
        *(float4*)(sA + rr * 68 + c4 * 4) = v;
    }
    __syncthreads();

    const int tx = tid & 15;
    const int ty = tid >> 4;
    const int fbase = tx * 8;

    float acc[8][8];
    float bj[8];
    #pragma unroll
    for (int j = 0; j < 8; j++) bj[j] = __ldg(&bg[fbase + j]);
    #pragma unroll
    for (int i = 0; i < 8; i++)
        #pragma unroll
        for (int j = 0; j < 8; j++) acc[i][j] = bj[j];

    for (int k4 = 0; k4 < 16; k4++) {
        const int k0 = k4 * 4;
        float4 wv[4][2];
        #pragma unroll
        for (int kk = 0; kk < 4; kk++) {
            wv[kk][0] = *(const float4*)(sW + (k0 + kk) * 128 + fbase);
            wv[kk][1] = *(const float4*)(sW + (k0 + kk) * 128 + fbase + 4);
        }
        #pragma unroll
        for (int i = 0; i < 8; i++) {
            float4 av = *(const float4*)(sA + (ty + 8 * i) * 68 + k0);
            float a4[4] = {av.x, av.y, av.z, av.w};
            #pragma unroll
            for (int kk = 0; kk < 4; kk++) {
                const float* w = &wv[kk][0].x;
                #pragma unroll
                for (int j = 0; j < 8; j++)
                    acc[i][j] = fmaf(a4[kk], w[j], acc[i][j]);
            }
        }
    }

    #pragma unroll
    for (int i = 0; i < 8; i++) {
        int n = nbase + ty + 8 * i;
        if (n < N_NODES) {
            float4 v0, v1;
            v0.x = acc[i][0]; v0.y = acc[i][1]; v0.z = acc[i][2]; v0.w = acc[i][3];
            v1.x = acc[i][4]; v1.y = acc[i][5]; v1.z = acc[i][6]; v1.w = acc[i][7];
            *(float4*)(out + (size_t)n * 128 + fbase)     = v0;
            *(float4*)(out + (size_t)n * 128 + fbase + 4) = v1;
        }
    }
}

// ---------------------------------------------------------------------------
extern "C" void kernel_launch(void* const* d_in, const int* in_sizes, int n_in,
                              void* d_out, int out_size) {
    const float* x   = (const float*)d_in[0];
    const float* pos = (const float*)d_in[1];
    const void*  ei  = d_in[2];
    const float* W1  = (const float*)d_in[3];
    const float* b1  = (const float*)d_in[4];
    const float* W2  = (const float*)d_in[5];
    const float* b2  = (const float*)d_in[6];
    const float* Wg  = (const float*)d_in[7];
    const float* bg  = (const float*)d_in[8];
    float* out = (float*)d_out;

    cudaFuncSetAttribute(k_msg, cudaFuncAttributeMaxDynamicSharedMemorySize, SMEM_MSG_BYTES);
    cudaFuncSetAttribute(k_out, cudaFuncAttributeMaxDynamicSharedMemorySize, SMEM_OUT_BYTES);

    k_detect<<<1, 1024>>>((const int*)ei);
    k_zero<<<(N_NODES * 64 / 4 + 255) / 256, 256>>>();
    k_msg<<<(M_TOTAL + TILE_E - 1) / TILE_E, 128, SMEM_MSG_BYTES>>>(x, pos, ei, W1, b1, W2, b2);
    k_out<<<(N_NODES + 63) / 64, 128, SMEM_OUT_BYTES>>>(Wg, bg, out);
}